// round 3
// baseline (speedup 1.0000x reference)
#include <cuda_runtime.h>
#include <cstdint>

#define T_STEPS 256
#define BATCH   64
#define HID     512
#define OUTD    4

// Recurrence decomposition: 8 batch groups x 16 column-slice CTAs = 128 CTAs
#define GB 8
#define GJ 16
#define RH (BATCH / GB)   // 8 rows per group
#define CJ (HID / GJ)     // 32 cols per CTA

// Device-global scratch (no cudaMalloc allowed)
__device__ __align__(16) float g_xw[T_STEPS * BATCH * HID];   // [T][B][H]
__device__ __align__(16) float g_h[2][BATCH][HID];            // double-buffered h
__device__ unsigned int g_flags[GB][GJ];                      // monotonic counters

__device__ __forceinline__ unsigned int ld_acquire_u32(const unsigned int* p) {
    unsigned int v;
    asm volatile("ld.acquire.gpu.global.u32 %0, [%1];" : "=r"(v) : "l"(p) : "memory");
    return v;
}
__device__ __forceinline__ void st_release_u32(unsigned int* p, unsigned int v) {
    asm volatile("st.release.gpu.global.u32 [%0], %1;" :: "l"(p), "r"(v) : "memory");
}

// Accurate even under --use_fast_math (expf -> __expf ~2^-21 rel error).
__device__ __forceinline__ float tanh_accurate(float z) {
    return 1.0f - 2.0f / (expf(2.0f * z) + 1.0f);
}

// ---------------------------------------------------------------------------
// Kernel 1: g_xw[t][b][:] = emb[x[b][t]] @ W_ih^T + b_ih
// 64x64 tile over K=512, BK=16, 256 threads, 4x4 microtile.
// ---------------------------------------------------------------------------
__global__ void proj_kernel(const int* __restrict__ x,
                            const float* __restrict__ emb,
                            const float* __restrict__ W_ih,
                            const float* __restrict__ b_ih)
{
    __shared__ float As[16][64];
    __shared__ float Bs[16][64];
    __shared__ int   idx[64];

    const int tid = threadIdx.x;
    const int m0 = blockIdx.y * 64;   // row = b*T + t
    const int j0 = blockIdx.x * 64;   // hidden column

    if (tid < 64) idx[tid] = x[m0 + tid];
    __syncthreads();

    const int lm = tid >> 2;
    const int lq = tid & 3;
    const int ty = tid >> 4;
    const int tx = tid & 15;

    float acc[4][4];
#pragma unroll
    for (int i = 0; i < 4; ++i)
#pragma unroll
        for (int j = 0; j < 4; ++j) acc[i][j] = 0.0f;

    const size_t arow = (size_t)idx[lm] * HID;
    const size_t brow = (size_t)(j0 + lm) * HID;

    for (int k0 = 0; k0 < HID; k0 += 16) {
        float4 av = *(const float4*)(emb  + arow + k0 + 4 * lq);
        float4 bv = *(const float4*)(W_ih + brow + k0 + 4 * lq);
        As[4*lq+0][lm] = av.x; As[4*lq+1][lm] = av.y;
        As[4*lq+2][lm] = av.z; As[4*lq+3][lm] = av.w;
        Bs[4*lq+0][lm] = bv.x; Bs[4*lq+1][lm] = bv.y;
        Bs[4*lq+2][lm] = bv.z; Bs[4*lq+3][lm] = bv.w;
        __syncthreads();

#pragma unroll
        for (int k = 0; k < 16; ++k) {
            float a[4], b[4];
            *(float4*)a = *(const float4*)(&As[k][4 * ty]);
            *(float4*)b = *(const float4*)(&Bs[k][4 * tx]);
#pragma unroll
            for (int i = 0; i < 4; ++i)
#pragma unroll
                for (int j = 0; j < 4; ++j)
                    acc[i][j] += a[i] * b[j];
        }
        __syncthreads();
    }

    float4 bi = *(const float4*)(b_ih + j0 + 4 * tx);
#pragma unroll
    for (int i = 0; i < 4; ++i) {
        int m = m0 + 4 * ty + i;
        int b = m >> 8;      // T = 256
        int t = m & 255;
        float4 v;
        v.x = acc[i][0] + bi.x; v.y = acc[i][1] + bi.y;
        v.z = acc[i][2] + bi.z; v.w = acc[i][3] + bi.w;
        *(float4*)(&g_xw[((size_t)t * BATCH + b) * HID + j0 + 4 * tx]) = v;
    }
}

// ---------------------------------------------------------------------------
// Kernel 2: persistent recurrence + FC. 128 CTAs x 256 threads.
// Warp w (k-chunk [64w, 64w+64)) consumes exactly producer CTAs 2w and 2w+1:
// it spins on its own two flags, copies its own 2KB of h, computes without
// any CTA-wide barrier before the psum reduce.
// Thread (j = tid&31, kc = tid>>5) holds W_hh[j0+j][64*kc..+63] in registers.
// ---------------------------------------------------------------------------
__global__ void rec_kernel(const float* __restrict__ W_hh,
                           const float* __restrict__ b_hh,
                           const float* __restrict__ W_fc,
                           const float* __restrict__ b_fc,
                           float* __restrict__ out)
{
    __shared__ float hs[RH * HID];            // 8x512 h rows (16 KB)
    __shared__ float psum[RH * 8 * 32];       // [row][kc][j] (8 KB)

    const int tid  = threadIdx.x;
    const int lane = tid & 31;
    const int wrp  = tid >> 5;                // 0..7 == k-chunk kc
    const int g  = blockIdx.x >> 4;
    const int jg = blockIdx.x & 15;
    const int r0 = g * RH;
    const int j0 = jg * CJ;

    const int j  = lane;   // compute: column within slice
    const int kc = wrp;    // compute: 64-wide k chunk
    const int rr = wrp;    // reduce: row
    const int jj = lane;   // reduce: column

    // W_hh slice to registers: 64 floats (reused 256 steps x 8 rows)
    float wreg[64];
    {
        const float* wrow = W_hh + (size_t)(j0 + j) * HID + kc * 64;
#pragma unroll
        for (int q = 0; q < 16; ++q) {
            float4 v = *(const float4*)(wrow + 4 * q);
            wreg[4*q+0] = v.x; wreg[4*q+1] = v.y;
            wreg[4*q+2] = v.z; wreg[4*q+3] = v.w;
        }
    }
    const float bhh = b_hh[j0 + jj];

    // Initialize out with bias (one CTA per group; ordered before peers' FC
    // atomicAdds via the step-sync chain).
    if (jg == 0 && tid < RH * OUTD) {
        int r = tid >> 2, o = tid & 3;
        out[(r0 + r) * OUTD + o] = b_fc[o];
    }

    // Monotonic flag base (single writer per flag; survives graph replays).
    const unsigned int base = g_flags[g][jg];

    // Production 0: h0 = 0 (thread (rr,jj) owns element (r0+rr, j0+jj)).
    g_h[0][r0 + rr][j0 + jj] = 0.0f;
    __syncthreads();
    if (tid == 0) st_release_u32(&g_flags[g][jg], base + 1u);

    float hval = 0.0f;

    for (int p = 1; p <= T_STEPS; ++p) {
        // xw for this step is independent of producers — issue early.
        const float xwv = g_xw[((size_t)(p - 1) * BATCH + (r0 + rr)) * HID + j0 + jj];

        const float* hsrc = &g_h[(p - 1) & 1][r0][0];
        const unsigned int tgt = base + (unsigned int)p;

        // Per-warp: wait for my two producer chunks and copy them (2 KB).
#pragma unroll
        for (int i = 0; i < 2; ++i) {
            const int c = 2 * wrp + i;                 // producer CTA index
            if (lane == 0) {
                while (ld_acquire_u32(&g_flags[g][c]) < tgt) { }
            }
            __syncwarp();
            // chunk c = cols [32c, 32c+32) for 8 rows: 64 float4, 2 per lane
#pragma unroll
            for (int q = 0; q < 2; ++q) {
                int f = lane + 32 * q;                 // 0..63
                int r = f >> 3;                        // row 0..7
                int cq = f & 7;                        // float4 within row
                *(float4*)(&hs[r * HID + c * 32 + cq * 4]) =
                    *(const float4*)(hsrc + (size_t)r * HID + c * 32 + cq * 4);
            }
        }
        __syncwarp();

        // Partial dot products over this warp's 64-wide k chunk, 8 rows.
        // All lanes read the same hs address -> pure broadcast LDS.
#pragma unroll
        for (int r = 0; r < RH; ++r) {
            const float4* hrow = (const float4*)(hs + r * HID + kc * 64);
            float a = 0.0f;
#pragma unroll
            for (int q = 0; q < 16; ++q) {
                float4 hv = hrow[q];
                a += hv.x * wreg[4*q+0] + hv.y * wreg[4*q+1]
                   + hv.z * wreg[4*q+2] + hv.w * wreg[4*q+3];
            }
            psum[(r * 8 + kc) * 32 + j] = a;
        }
        __syncthreads();

        // Reduce 8 k-chunk partials, add xw + bias, tanh, publish.
        float z = bhh + xwv;
#pragma unroll
        for (int c = 0; c < 8; ++c)
            z += psum[(rr * 8 + c) * 32 + jj];
        hval = tanh_accurate(z);
        g_h[p & 1][r0 + rr][j0 + jj] = hval;
        __syncthreads();
        if (tid == 0) st_release_u32(&g_flags[g][jg], base + (unsigned int)p + 1u);
    }

    // FC: out[b][o] += sum over this slice of hT * W_fc. hval = hT(r0+rr, j0+jj).
    float partial[OUTD];
#pragma unroll
    for (int o = 0; o < OUTD; ++o)
        partial[o] = hval * W_fc[o * HID + j0 + jj];
#pragma unroll
    for (int o = 0; o < OUTD; ++o)
#pragma unroll
        for (int s = 16; s > 0; s >>= 1)
            partial[o] += __shfl_xor_sync(0xFFFFFFFFu, partial[o], s);
    if (jj == 0) {
#pragma unroll
        for (int o = 0; o < OUTD; ++o)
            atomicAdd(&out[(r0 + rr) * OUTD + o], partial[o]);
    }
}

extern "C" void kernel_launch(void* const* d_in, const int* in_sizes, int n_in,
                              void* d_out, int out_size)
{
    const int*   x    = (const int*)  d_in[0];
    const float* emb  = (const float*)d_in[1];
    const float* W_ih = (const float*)d_in[2];
    const float* W_hh = (const float*)d_in[3];
    const float* b_ih = (const float*)d_in[4];
    const float* b_hh = (const float*)d_in[5];
    const float* W_fc = (const float*)d_in[6];
    const float* b_fc = (const float*)d_in[7];
    float* out = (float*)d_out;
    (void)in_sizes; (void)n_in; (void)out_size;

    proj_kernel<<<dim3(HID / 64, (BATCH * T_STEPS) / 64), 256>>>(x, emb, W_ih, b_ih);
    rec_kernel<<<GB * GJ, 256>>>(W_hh, b_hh, W_fc, b_fc, out);
}

// round 4
// speedup vs baseline: 1.7690x; 1.7690x over previous
#include <cuda_runtime.h>
#include <cstdint>

#define T_STEPS 256
#define BATCH   64
#define HID     512
#define OUTD    4

#define CLUSTER 8          // CTAs per cluster
#define RPC     4          // batch rows per cluster (64/16 clusters)
#define CPC     64         // hidden columns per CTA (512/8)

// Global scratch (no cudaMalloc allowed)
__device__ __align__(16) float g_xw[T_STEPS * BATCH * HID];   // [T][B][H]

__device__ __forceinline__ uint32_t smem_u32(const void* p) {
    uint32_t a;
    asm("{ .reg .u64 t; cvta.to.shared.u64 t, %1; cvt.u32.u64 %0, t; }"
        : "=r"(a) : "l"(p));
    return a;
}
__device__ __forceinline__ void st_dsmem_f32(uint32_t laddr, int crank, float v) {
    uint32_t raddr;
    asm volatile("mapa.shared::cluster.u32 %0, %1, %2;"
                 : "=r"(raddr) : "r"(laddr), "r"(crank));
    asm volatile("st.shared::cluster.f32 [%0], %1;"
                 :: "r"(raddr), "f"(v) : "memory");
}

// Accurate even under --use_fast_math (expf -> __expf ~2^-21 rel error).
__device__ __forceinline__ float tanh_accurate(float z) {
    return 1.0f - 2.0f / (expf(2.0f * z) + 1.0f);
}

// ---------------------------------------------------------------------------
// Kernel 1: g_xw[t][b][:] = emb[x[b][t]] @ W_ih^T + b_ih
// 64x64 tile over K=512, BK=16, 256 threads, 4x4 microtile.
// ---------------------------------------------------------------------------
__global__ void proj_kernel(const int* __restrict__ x,
                            const float* __restrict__ emb,
                            const float* __restrict__ W_ih,
                            const float* __restrict__ b_ih)
{
    __shared__ float As[16][64];
    __shared__ float Bs[16][64];
    __shared__ int   idx[64];

    const int tid = threadIdx.x;
    const int m0 = blockIdx.y * 64;   // row = b*T + t
    const int j0 = blockIdx.x * 64;   // hidden column

    if (tid < 64) idx[tid] = x[m0 + tid];
    __syncthreads();

    const int lm = tid >> 2;
    const int lq = tid & 3;
    const int ty = tid >> 4;
    const int tx = tid & 15;

    float acc[4][4];
#pragma unroll
    for (int i = 0; i < 4; ++i)
#pragma unroll
        for (int j = 0; j < 4; ++j) acc[i][j] = 0.0f;

    const size_t arow = (size_t)idx[lm] * HID;
    const size_t brow = (size_t)(j0 + lm) * HID;

    for (int k0 = 0; k0 < HID; k0 += 16) {
        float4 av = *(const float4*)(emb  + arow + k0 + 4 * lq);
        float4 bv = *(const float4*)(W_ih + brow + k0 + 4 * lq);
        As[4*lq+0][lm] = av.x; As[4*lq+1][lm] = av.y;
        As[4*lq+2][lm] = av.z; As[4*lq+3][lm] = av.w;
        Bs[4*lq+0][lm] = bv.x; Bs[4*lq+1][lm] = bv.y;
        Bs[4*lq+2][lm] = bv.z; Bs[4*lq+3][lm] = bv.w;
        __syncthreads();

#pragma unroll
        for (int k = 0; k < 16; ++k) {
            float a[4], b[4];
            *(float4*)a = *(const float4*)(&As[k][4 * ty]);
            *(float4*)b = *(const float4*)(&Bs[k][4 * tx]);
#pragma unroll
            for (int i = 0; i < 4; ++i)
#pragma unroll
                for (int j = 0; j < 4; ++j)
                    acc[i][j] += a[i] * b[j];
        }
        __syncthreads();
    }

    float4 bi = *(const float4*)(b_ih + j0 + 4 * tx);
#pragma unroll
    for (int i = 0; i < 4; ++i) {
        int m = m0 + 4 * ty + i;
        int b = m >> 8;      // T = 256
        int t = m & 255;
        float4 v;
        v.x = acc[i][0] + bi.x; v.y = acc[i][1] + bi.y;
        v.z = acc[i][2] + bi.z; v.w = acc[i][3] + bi.w;
        *(float4*)(&g_xw[((size_t)t * BATCH + b) * HID + j0 + 4 * tx]) = v;
    }
}

// ---------------------------------------------------------------------------
// Kernel 2: recurrence + FC. 16 clusters x 8 CTAs x 512 threads.
// Cluster cl: batch rows [4cl, 4cl+4). CTA rank: columns [64*rank, 64*rank+64).
// Full h (4x512) kept double-buffered in EVERY CTA's smem; new h values are
// pushed to all cluster peers via DSMEM; one barrier.cluster per step.
// Thread (j = tid&63, kc = tid>>6) holds W_hh[j0+j][64*kc..+63] in registers.
// ---------------------------------------------------------------------------
__global__ void __cluster_dims__(CLUSTER, 1, 1) __launch_bounds__(512, 1)
rec_kernel(const float* __restrict__ W_hh,
           const float* __restrict__ b_hh,
           const float* __restrict__ W_fc,
           const float* __restrict__ b_fc,
           float* __restrict__ out)
{
    __shared__ float hs[2][RPC][HID];        // 16 KB: full h, double-buffered
    __shared__ float psum[RPC][8][CPC];      // 8 KB: k-chunk partials

    const int tid  = threadIdx.x;
    const int rank = blockIdx.x & (CLUSTER - 1);
    const int cl   = blockIdx.x / CLUSTER;
    const int r0 = cl * RPC;
    const int j0 = rank * CPC;

    const int j  = tid & 63;    // compute: column within slice
    const int kc = tid >> 6;    // compute: 64-wide k chunk (0..7)
    const int rr = tid >> 6;    // reduce (tid<256): row 0..3
    const int jj = tid & 63;    // reduce: column

    // W_hh slice to registers (reused 256 steps x 4 rows)
    float wreg[64];
    {
        const float* wrow = W_hh + (size_t)(j0 + j) * HID + kc * 64;
#pragma unroll
        for (int q = 0; q < 16; ++q) {
            float4 v = *(const float4*)(wrow + 4 * q);
            wreg[4*q+0] = v.x; wreg[4*q+1] = v.y;
            wreg[4*q+2] = v.z; wreg[4*q+3] = v.w;
        }
    }
    const float bhh = b_hh[j0 + jj];

    // h0 = 0 in this CTA's local buffer 0.
    {
        float* h0 = &hs[0][0][0];
        for (int i = tid; i < RPC * HID; i += 512) h0[i] = 0.0f;
    }
    __syncthreads();

    for (int p = 1; p <= T_STEPS; ++p) {
        const int rb = (p - 1) & 1;
        const int wb = p & 1;

        // xw element for this step (reducers only) — issue early.
        float xwv = 0.0f;
        if (tid < 256)
            xwv = g_xw[((size_t)(p - 1) * BATCH + (r0 + rr)) * HID + j0 + jj];

        // Partial dot products over this thread's 64-wide k chunk, 4 rows.
        // All lanes of a warp read the same hs address -> pure broadcast LDS.
#pragma unroll
        for (int r = 0; r < RPC; ++r) {
            const float4* hrow = (const float4*)(&hs[rb][r][kc * 64]);
            float a = 0.0f;
#pragma unroll
            for (int q = 0; q < 16; ++q) {
                float4 hv = hrow[q];
                a += hv.x * wreg[4*q+0] + hv.y * wreg[4*q+1]
                   + hv.z * wreg[4*q+2] + hv.w * wreg[4*q+3];
            }
            psum[r][kc][j] = a;
        }
        __syncthreads();

        // Reduce 8 partials, add xw + bias, tanh, push to all cluster CTAs.
        if (tid < 256) {
            float z = bhh + xwv;
#pragma unroll
            for (int c = 0; c < 8; ++c)
                z += psum[rr][c][jj];
            const float hval = tanh_accurate(z);
            const uint32_t laddr = smem_u32(&hs[wb][rr][j0 + jj]);
#pragma unroll
            for (int c = 0; c < CLUSTER; ++c)
                st_dsmem_f32(laddr, c, hval);
        }

        // One cluster barrier per step: release my pushes, acquire peers'.
        // Also serves as the CTA-wide barrier for psum/hs reuse.
        asm volatile("barrier.cluster.arrive.aligned;" ::: "memory");
        asm volatile("barrier.cluster.wait.aligned;"   ::: "memory");
    }

    // FC: rank 0 of each cluster has full h_T (buffer T&1 = 0) in local smem.
    // Warp w (0..15): row r = w>>2, output o = w&3.
    if (rank == 0 && tid < 512) {
        const int w    = tid >> 5;
        const int lane = tid & 31;
        const int r = w >> 2;
        const int o = w & 3;
        float s = 0.0f;
        const float* hrow = &hs[T_STEPS & 1][r][0];
        const float* wf   = W_fc + (size_t)o * HID;
#pragma unroll
        for (int k = lane; k < HID; k += 32)
            s += hrow[k] * wf[k];
#pragma unroll
        for (int sh = 16; sh > 0; sh >>= 1)
            s += __shfl_xor_sync(0xFFFFFFFFu, s, sh);
        if (lane == 0)
            out[(r0 + r) * OUTD + o] = s + b_fc[o];
    }
}

extern "C" void kernel_launch(void* const* d_in, const int* in_sizes, int n_in,
                              void* d_out, int out_size)
{
    const int*   x    = (const int*)  d_in[0];
    const float* emb  = (const float*)d_in[1];
    const float* W_ih = (const float*)d_in[2];
    const float* W_hh = (const float*)d_in[3];
    const float* b_ih = (const float*)d_in[4];
    const float* b_hh = (const float*)d_in[5];
    const float* W_fc = (const float*)d_in[6];
    const float* b_fc = (const float*)d_in[7];
    float* out = (float*)d_out;
    (void)in_sizes; (void)n_in; (void)out_size;

    proj_kernel<<<dim3(HID / 64, (BATCH * T_STEPS) / 64), 256>>>(x, emb, W_ih, b_ih);
    rec_kernel<<<BATCH / RPC * CLUSTER, 512>>>(W_hh, b_hh, W_fc, b_fc, out);
}